// round 7
// baseline (speedup 1.0000x reference)
#include <cuda_runtime.h>
#include <cuda_bf16.h>
#include <cstdint>

// B=4, T=2048, E=768, H=64 — causal single-head attention, fp32 out.
// pre-split x/W -> bf16 hi/lo | tensor GEMM (cp.async double-buffered,
// 32x32 warp tiles) | split-K(4) fused flash attention | combine.

#define BATCH 4
#define SEQ   2048
#define EMB   768
#define HDIM  64
#define ROWS  (BATCH*SEQ)   // 8192
#define NCHUNK 4

__device__ __nv_bfloat16 g_xh[ROWS*EMB], g_xl[ROWS*EMB];
__device__ __nv_bfloat16 g_wh[3][EMB*HDIM], g_wl[3][EMB*HDIM];
__device__ __nv_bfloat16 g_qh[ROWS*HDIM], g_ql[ROWS*HDIM];
__device__ __nv_bfloat16 g_kh[ROWS*HDIM], g_kl[ROWS*HDIM];
__device__ __nv_bfloat16 g_vh[ROWS*HDIM], g_vl[ROWS*HDIM];
__device__ float g_pm[NCHUNK][ROWS], g_pl[NCHUNK][ROWS], g_po[NCHUNK][ROWS*HDIM];

// ---------------- helpers (sm_80+ baseline PTX) ------------------------------
__device__ __forceinline__ void ldsm_x4(uint32_t* r, const void* p) {
    uint32_t a = (uint32_t)__cvta_generic_to_shared(p);
    asm volatile("ldmatrix.sync.aligned.m8n8.x4.shared.b16 {%0,%1,%2,%3}, [%4];"
                 : "=r"(r[0]), "=r"(r[1]), "=r"(r[2]), "=r"(r[3]) : "r"(a));
}
__device__ __forceinline__ void ldsm_x4_t(uint32_t* r, const void* p) {
    uint32_t a = (uint32_t)__cvta_generic_to_shared(p);
    asm volatile("ldmatrix.sync.aligned.m8n8.x4.trans.shared.b16 {%0,%1,%2,%3}, [%4];"
                 : "=r"(r[0]), "=r"(r[1]), "=r"(r[2]), "=r"(r[3]) : "r"(a));
}
__device__ __forceinline__ void mma16816(float* c, const uint32_t* a,
                                         uint32_t b0, uint32_t b1) {
    asm volatile("mma.sync.aligned.m16n8k16.row.col.f32.bf16.bf16.f32 "
                 "{%0,%1,%2,%3}, {%4,%5,%6,%7}, {%8,%9}, {%0,%1,%2,%3};"
                 : "+f"(c[0]), "+f"(c[1]), "+f"(c[2]), "+f"(c[3])
                 : "r"(a[0]), "r"(a[1]), "r"(a[2]), "r"(a[3]), "r"(b0), "r"(b1));
}
__device__ __forceinline__ uint32_t pack_bf16x2(float lo, float hi) {
    uint32_t r;
    asm("cvt.rn.bf16x2.f32 %0, %1, %2;" : "=r"(r) : "f"(hi), "f"(lo));
    return r;
}
__device__ __forceinline__ void split2(float p0, float p1, uint32_t& hi, uint32_t& lo) {
    uint32_t h = pack_bf16x2(p0, p1);
    __nv_bfloat162 hb = *reinterpret_cast<__nv_bfloat162*>(&h);
    float2 hf = __bfloat1622float2(hb);
    lo = pack_bf16x2(p0 - hf.x, p1 - hf.y);
    hi = h;
}
__device__ __forceinline__ void cp16(void* dst, const void* src) {
    uint32_t d = (uint32_t)__cvta_generic_to_shared(dst);
    asm volatile("cp.async.cg.shared.global [%0], [%1], 16;" :: "r"(d), "l"(src));
}

// ---------------------------------------------------------------------------
// K0a: split x -> bf16 hi/lo
// ---------------------------------------------------------------------------
__global__ __launch_bounds__(256)
void split_x(const float* __restrict__ x)
{
    int i = (blockIdx.x * 256 + threadIdx.x) * 4;
    float4 v = *(const float4*)(x + i);
    uint32_t h0, l0, h1, l1;
    split2(v.x, v.y, h0, l0);
    split2(v.z, v.w, h1, l1);
    *(uint32_t*)&g_xh[i]     = h0;  *(uint32_t*)&g_xh[i + 2] = h1;
    *(uint32_t*)&g_xl[i]     = l0;  *(uint32_t*)&g_xl[i + 2] = l1;
}

// K0b: split W (Q weight pre-scaled by 1/sqrt(E))
__global__ __launch_bounds__(256)
void split_w(const float* __restrict__ Wk,
             const float* __restrict__ Wq,
             const float* __restrict__ Wv)
{
    int y = blockIdx.y;
    const float* W = (y == 0) ? Wq : (y == 1) ? Wk : Wv;
    float sc = (y == 0) ? rsqrtf((float)EMB) : 1.0f;
    int i = (blockIdx.x * 256 + threadIdx.x) * 4;
    float4 v = *(const float4*)(W + i);
    uint32_t h0, l0, h1, l1;
    split2(v.x * sc, v.y * sc, h0, l0);
    split2(v.z * sc, v.w * sc, h1, l1);
    *(uint32_t*)&g_wh[y][i]     = h0;  *(uint32_t*)&g_wh[y][i + 2] = h1;
    *(uint32_t*)&g_wl[y][i]     = l0;  *(uint32_t*)&g_wl[y][i + 2] = l1;
}

// ---------------------------------------------------------------------------
// K1: QKV GEMM. CTA 128x64, 256 thr = 8 warps (4 row-groups x 2 col-groups),
// warp tile 32x32, k-chunk 32, 2-stage cp.async double buffer.
// smem stage: Xh[128][40] Xl[128][40] Wh[32][72] Wl[32][72]  (bf16)
// ---------------------------------------------------------------------------
#define BM   128
#define BKC  32
#define XSTR 40
#define WSTR 72
#define STG_ELEMS (2*BM*XSTR + 2*BKC*WSTR)   // 14848 bf16 = 29696 B

extern __shared__ __nv_bfloat16 g_sm[];

__device__ __forceinline__ void gemm_load_stage(__nv_bfloat16* st, int widx,
                                                int m0, int kc0, int t)
{
    __nv_bfloat16* Xh = st;
    __nv_bfloat16* Xl = st + BM * XSTR;
    __nv_bfloat16* Wh = st + 2 * BM * XSTR;
    __nv_bfloat16* Wl = Wh + BKC * WSTR;

    int row = t >> 1, half = t & 1;
    const __nv_bfloat16* sxh = g_xh + (size_t)(m0 + row) * EMB + kc0 + half * 16;
    const __nv_bfloat16* sxl = g_xl + (size_t)(m0 + row) * EMB + kc0 + half * 16;
    cp16(&Xh[row * XSTR + half * 16 + 0], sxh + 0);
    cp16(&Xh[row * XSTR + half * 16 + 8], sxh + 8);
    cp16(&Xl[row * XSTR + half * 16 + 0], sxl + 0);
    cp16(&Xl[row * XSTR + half * 16 + 8], sxl + 8);

    int wrow = t >> 3, col8 = (t & 7) * 8;   // 32 rows x 64 cols
    cp16(&Wh[wrow * WSTR + col8], g_wh[widx] + (size_t)(kc0 + wrow) * HDIM + col8);
    cp16(&Wl[wrow * WSTR + col8], g_wl[widx] + (size_t)(kc0 + wrow) * HDIM + col8);
}

__global__ __launch_bounds__(256)
void qkv_gemm_mma()
{
    const int widx = blockIdx.y;
    const int m0   = blockIdx.x * BM;
    const int t    = threadIdx.x;
    const int w    = t >> 5;
    const int lane = t & 31;
    const int rg   = w >> 1;        // row group 0..3
    const int cg   = w & 1;         // col group 0..1

    const int lrow = (lane & 7) + ((lane >> 3) & 1) * 8;
    const int lcol = (lane >> 4) * 8;

    float c[2][4][4];
    #pragma unroll
    for (int mt = 0; mt < 2; mt++)
        #pragma unroll
        for (int j = 0; j < 4; j++)
            #pragma unroll
            for (int e = 0; e < 4; e++) c[mt][j][e] = 0.f;

    const int NC = EMB / BKC;   // 24

    gemm_load_stage(g_sm, widx, m0, 0, t);
    asm volatile("cp.async.commit_group;");

    for (int kc = 0; kc < NC; kc++) {
        if (kc + 1 < NC) {
            gemm_load_stage(g_sm + ((kc + 1) & 1) * STG_ELEMS, widx, m0, (kc + 1) * BKC, t);
            asm volatile("cp.async.commit_group;");
            asm volatile("cp.async.wait_group 1;");
        } else {
            asm volatile("cp.async.wait_group 0;");
        }
        __syncthreads();

        __nv_bfloat16* st = g_sm + (kc & 1) * STG_ELEMS;
        __nv_bfloat16* Xh = st;
        __nv_bfloat16* Xl = st + BM * XSTR;
        __nv_bfloat16* Wh = st + 2 * BM * XSTR;
        __nv_bfloat16* Wl = Wh + BKC * WSTR;

        uint32_t ah[2][2][4], al[2][2][4];
        #pragma unroll
        for (int mt = 0; mt < 2; mt++)
            #pragma unroll
            for (int kt = 0; kt < 2; kt++) {
                ldsm_x4(ah[mt][kt], &Xh[(rg * 32 + mt * 16 + lrow) * XSTR + kt * 16 + lcol]);
                ldsm_x4(al[mt][kt], &Xl[(rg * 32 + mt * 16 + lrow) * XSTR + kt * 16 + lcol]);
            }

        #pragma unroll
        for (int kt = 0; kt < 2; kt++) {
            #pragma unroll
            for (int nt = 0; nt < 2; nt++) {
                uint32_t bh[4], bl[4];
                ldsm_x4_t(bh, &Wh[(kt * 16 + lrow) * WSTR + cg * 32 + nt * 16 + lcol]);
                ldsm_x4_t(bl, &Wl[(kt * 16 + lrow) * WSTR + cg * 32 + nt * 16 + lcol]);
                #pragma unroll
                for (int mt = 0; mt < 2; mt++) {
                    mma16816(c[mt][nt * 2],     ah[mt][kt], bh[0], bh[1]);
                    mma16816(c[mt][nt * 2],     ah[mt][kt], bl[0], bl[1]);
                    mma16816(c[mt][nt * 2],     al[mt][kt], bh[0], bh[1]);
                    mma16816(c[mt][nt * 2 + 1], ah[mt][kt], bh[2], bh[3]);
                    mma16816(c[mt][nt * 2 + 1], ah[mt][kt], bl[2], bl[3]);
                    mma16816(c[mt][nt * 2 + 1], al[mt][kt], bh[2], bh[3]);
                }
            }
        }
        __syncthreads();
    }

    __nv_bfloat16* oh = (widx == 0) ? g_qh : (widx == 1) ? g_kh : g_vh;
    __nv_bfloat16* ol = (widx == 0) ? g_ql : (widx == 1) ? g_kl : g_vl;

    #pragma unroll
    for (int mt = 0; mt < 2; mt++) {
        int r0 = m0 + rg * 32 + mt * 16 + (lane >> 2);
        #pragma unroll
        for (int j = 0; j < 4; j++) {
            int col = cg * 32 + j * 8 + 2 * (lane & 3);
            uint32_t h, l;
            split2(c[mt][j][0], c[mt][j][1], h, l);
            *(uint32_t*)&oh[(size_t)r0 * HDIM + col] = h;
            *(uint32_t*)&ol[(size_t)r0 * HDIM + col] = l;
            split2(c[mt][j][2], c[mt][j][3], h, l);
            *(uint32_t*)&oh[(size_t)(r0 + 8) * HDIM + col] = h;
            *(uint32_t*)&ol[(size_t)(r0 + 8) * HDIM + col] = l;
        }
    }
}

// ---------------------------------------------------------------------------
// K2: split-K(4) fused flash attention. CTA = (q-tile of 64 rows, chunk 0..3);
// chunk processes key-blocks kb = chunk, chunk+4, ...  Unnormalized partials.
// ---------------------------------------------------------------------------
#define BQ  64
#define BK  64
#define STR 72
#define NEG_BIG (-1e30f)

__global__ __launch_bounds__(128)
void attn_kernel()
{
    __shared__ __nv_bfloat16 sKh[BK * STR], sKl[BK * STR];
    __shared__ __nv_bfloat16 sVh[BK * STR], sVl[BK * STR];

    const int b     = blockIdx.y;
    const int tile  = blockIdx.x >> 2;    // 0..31
    const int chunk = blockIdx.x & 3;
    const int q0    = tile * BQ;
    const int t     = threadIdx.x;
    const int w     = t >> 5;
    const int lane  = t & 31;

    // ---- stage Q (hi/lo) through sKh/sKl into register A-frags ----
    {
        int row = t >> 1, half = t & 1;
        size_t g = (size_t)(b * SEQ + q0 + row) * HDIM + half * 32;
        const uint4* ph = (const uint4*)(g_qh + g);
        const uint4* pl = (const uint4*)(g_ql + g);
        #pragma unroll
        for (int i = 0; i < 4; i++) {
            *(uint4*)&sKh[row * STR + half * 32 + i * 8] = ph[i];
            *(uint4*)&sKl[row * STR + half * 32 + i * 8] = pl[i];
        }
    }
    __syncthreads();

    uint32_t qhf[4][4], qlf[4][4];
    {
        int lrow = (lane & 7) + ((lane >> 3) & 1) * 8;
        int lcol = (lane >> 4) * 8;
        #pragma unroll
        for (int kc = 0; kc < 4; kc++) {
            ldsm_x4(qhf[kc], &sKh[(w * 16 + lrow) * STR + kc * 16 + lcol]);
            ldsm_x4(qlf[kc], &sKl[(w * 16 + lrow) * STR + kc * 16 + lcol]);
        }
    }

    float m0 = NEG_BIG, m1 = NEG_BIG, l0 = 0.f, l1 = 0.f;
    float o[8][4];
    #pragma unroll
    for (int j = 0; j < 8; j++)
        #pragma unroll
        for (int e = 0; e < 4; e++) o[j][e] = 0.f;

    const int nkb = tile + 1;

    for (int kb = chunk; kb < nkb; kb += NCHUNK) {
        const int k0 = kb * BK;
        __syncthreads();
        {
            int row = t >> 1, half = t & 1;
            size_t g = (size_t)(b * SEQ + k0 + row) * HDIM + half * 32;
            const uint4* pkh = (const uint4*)(g_kh + g);
            const uint4* pkl = (const uint4*)(g_kl + g);
            const uint4* pvh = (const uint4*)(g_vh + g);
            const uint4* pvl = (const uint4*)(g_vl + g);
            #pragma unroll
            for (int i = 0; i < 4; i++) {
                int so = row * STR + half * 32 + i * 8;
                *(uint4*)&sKh[so] = pkh[i];
                *(uint4*)&sKl[so] = pkl[i];
                *(uint4*)&sVh[so] = pvh[i];
                *(uint4*)&sVl[so] = pvl[i];
            }
        }
        __syncthreads();

        // ---- S = Q K^T (bf16 x3) ----
        float c[8][4];
        #pragma unroll
        for (int j = 0; j < 8; j++)
            #pragma unroll
            for (int e = 0; e < 4; e++) c[j][e] = 0.f;

        #pragma unroll
        for (int kc = 0; kc < 4; kc++) {
            #pragma unroll
            for (int jp = 0; jp < 4; jp++) {
                int krow = 16 * jp + (lane & 7) + (lane >> 4) * 8;
                int kcol = kc * 16 + ((lane >> 3) & 1) * 8;
                uint32_t bh[4], bl[4];
                ldsm_x4(bh, &sKh[krow * STR + kcol]);
                ldsm_x4(bl, &sKl[krow * STR + kcol]);
                mma16816(c[2 * jp],     qhf[kc], bh[0], bh[1]);
                mma16816(c[2 * jp],     qhf[kc], bl[0], bl[1]);
                mma16816(c[2 * jp],     qlf[kc], bh[0], bh[1]);
                mma16816(c[2 * jp + 1], qhf[kc], bh[2], bh[3]);
                mma16816(c[2 * jp + 1], qhf[kc], bl[2], bl[3]);
                mma16816(c[2 * jp + 1], qlf[kc], bh[2], bh[3]);
            }
        }

        // ---- causal mask (diagonal block only) ----
        if (k0 == q0) {
            int r0g = q0 + w * 16 + (lane >> 2);
            #pragma unroll
            for (int j = 0; j < 8; j++) {
                int cg = k0 + 8 * j + 2 * (lane & 3);
                if (cg     > r0g)     c[j][0] = NEG_BIG;
                if (cg + 1 > r0g)     c[j][1] = NEG_BIG;
                if (cg     > r0g + 8) c[j][2] = NEG_BIG;
                if (cg + 1 > r0g + 8) c[j][3] = NEG_BIG;
            }
        }

        // ---- online softmax ----
        float mx0 = NEG_BIG, mx1 = NEG_BIG;
        #pragma unroll
        for (int j = 0; j < 8; j++) {
            mx0 = fmaxf(mx0, fmaxf(c[j][0], c[j][1]));
            mx1 = fmaxf(mx1, fmaxf(c[j][2], c[j][3]));
        }
        #pragma unroll
        for (int ox = 1; ox <= 2; ox <<= 1) {
            mx0 = fmaxf(mx0, __shfl_xor_sync(0xffffffffu, mx0, ox));
            mx1 = fmaxf(mx1, __shfl_xor_sync(0xffffffffu, mx1, ox));
        }
        float mn0 = fmaxf(m0, mx0), mn1 = fmaxf(m1, mx1);
        float corr0 = __expf(m0 - mn0), corr1 = __expf(m1 - mn1);
        m0 = mn0; m1 = mn1;

        float rs0 = 0.f, rs1 = 0.f;
        uint32_t aph[4][4], apl[4][4];
        #pragma unroll
        for (int j = 0; j < 8; j++) {
            float p00 = __expf(c[j][0] - mn0);
            float p01 = __expf(c[j][1] - mn0);
            float p10 = __expf(c[j][2] - mn1);
            float p11 = __expf(c[j][3] - mn1);
            rs0 += p00 + p01;
            rs1 += p10 + p11;
            int kc2 = j >> 1, sel = (j & 1) * 2;
            split2(p00, p01, aph[kc2][sel + 0], apl[kc2][sel + 0]);
            split2(p10, p11, aph[kc2][sel + 1], apl[kc2][sel + 1]);
        }
        #pragma unroll
        for (int ox = 1; ox <= 2; ox <<= 1) {
            rs0 += __shfl_xor_sync(0xffffffffu, rs0, ox);
            rs1 += __shfl_xor_sync(0xffffffffu, rs1, ox);
        }
        l0 = l0 * corr0 + rs0;
        l1 = l1 * corr1 + rs1;
        #pragma unroll
        for (int j = 0; j < 8; j++) {
            o[j][0] *= corr0; o[j][1] *= corr0;
            o[j][2] *= corr1; o[j][3] *= corr1;
        }

        // ---- O += P V (bf16 x3) ----
        #pragma unroll
        for (int kc2 = 0; kc2 < 4; kc2++) {
            #pragma unroll
            for (int up = 0; up < 4; up++) {
                int vrow = 16 * kc2 + (lane & 7) + ((lane >> 3) & 1) * 8;
                int vcol = 16 * up + (lane >> 4) * 8;
                uint32_t bvh[4], bvl[4];
                ldsm_x4_t(bvh, &sVh[vrow * STR + vcol]);
                ldsm_x4_t(bvl, &sVl[vrow * STR + vcol]);
                mma16816(o[2 * up],     aph[kc2], bvh[0], bvh[1]);
                mma16816(o[2 * up],     aph[kc2], bvl[0], bvl[1]);
                mma16816(o[2 * up],     apl[kc2], bvh[0], bvh[1]);
                mma16816(o[2 * up + 1], aph[kc2], bvh[2], bvh[3]);
                mma16816(o[2 * up + 1], aph[kc2], bvl[2], bvl[3]);
                mma16816(o[2 * up + 1], apl[kc2], bvh[2], bvh[3]);
            }
        }
    }

    // ---- write partials ----
    int rl0 = b * SEQ + q0 + w * 16 + (lane >> 2);
    if ((lane & 3) == 0) {
        g_pm[chunk][rl0]     = m0;  g_pl[chunk][rl0]     = l0;
        g_pm[chunk][rl0 + 8] = m1;  g_pl[chunk][rl0 + 8] = l1;
    }
    #pragma unroll
    for (int j = 0; j < 8; j++) {
        int col = 8 * j + 2 * (lane & 3);
        *(float2*)&g_po[chunk][(size_t)rl0 * HDIM + col]       = make_float2(o[j][0], o[j][1]);
        *(float2*)&g_po[chunk][(size_t)(rl0 + 8) * HDIM + col] = make_float2(o[j][2], o[j][3]);
    }
}

// ---------------------------------------------------------------------------
// K3: combine the NCHUNK split-K partials.
// ---------------------------------------------------------------------------
__global__ __launch_bounds__(256)
void combine_kernel(float* __restrict__ out)
{
    int idx = blockIdx.x * 256 + threadIdx.x;   // over ROWS*32
    int row = idx >> 5;
    int col = (idx & 31) * 2;

    float mx = NEG_BIG;
    #pragma unroll
    for (int i = 0; i < NCHUNK; i++) mx = fmaxf(mx, g_pm[i][row]);

    float l = 0.f, ox = 0.f, oy = 0.f;
    #pragma unroll
    for (int i = 0; i < NCHUNK; i++) {
        float s = __expf(g_pm[i][row] - mx);
        l += s * g_pl[i][row];
        float2 p = *(const float2*)&g_po[i][(size_t)row * HDIM + col];
        ox += s * p.x;
        oy += s * p.y;
    }
    float inv = 1.0f / l;
    *(float2*)&out[(size_t)row * HDIM + col] = make_float2(ox * inv, oy * inv);
}

// ---------------------------------------------------------------------------
extern "C" void kernel_launch(void* const* d_in, const int* in_sizes, int n_in,
                              void* d_out, int out_size)
{
    const float* x  = (const float*)d_in[0];
    const float* Wk = (const float*)d_in[1];
    const float* Wq = (const float*)d_in[2];
    const float* Wv = (const float*)d_in[3];
    float* out = (float*)d_out;

    split_x<<<(ROWS * EMB / 4) / 256, 256>>>(x);
    dim3 wgrid((EMB * HDIM / 4) / 256, 3);
    split_w<<<wgrid, 256>>>(Wk, Wq, Wv);

    const int gsmem = 2 * STG_ELEMS * (int)sizeof(__nv_bfloat16);   // 59392 B
    cudaFuncSetAttribute(qkv_gemm_mma, cudaFuncAttributeMaxDynamicSharedMemorySize, gsmem);
    dim3 ggrid(ROWS / BM, 3);
    qkv_gemm_mma<<<ggrid, 256, gsmem>>>();

    dim3 agrid((SEQ / BQ) * NCHUNK, BATCH);
    attn_kernel<<<agrid, 128>>>();

    combine_kernel<<<(ROWS * 32) / 256, 256>>>(out);
}

// round 8
// speedup vs baseline: 1.7823x; 1.7823x over previous
#include <cuda_runtime.h>
#include <cuda_fp16.h>
#include <cstdint>

// B=4, T=2048, E=768, H=64 — causal single-head attention, fp32 out.
// fp16 pipeline: split x/W -> hi/lo fp16 | GEMM (x3 terms, cp.async, BKC=64)
// -> q/k/v fp16 | plain-fp16 flash attention (BQ=128, split-K 2, cp.async)
// | combine.

#define BATCH 4
#define SEQ   2048
#define EMB   768
#define HDIM  64
#define ROWS  (BATCH*SEQ)   // 8192
#define NCHUNK 2

__device__ __half g_xh[ROWS*EMB], g_xl[ROWS*EMB];
__device__ __half g_wh[3][EMB*HDIM], g_wl[3][EMB*HDIM];
__device__ __half g_qh[ROWS*HDIM], g_kh[ROWS*HDIM], g_vh[ROWS*HDIM];
__device__ float g_pm[NCHUNK][ROWS], g_pl[NCHUNK][ROWS], g_po[NCHUNK][ROWS*HDIM];

// ---------------- helpers (sm_80+ baseline PTX) ------------------------------
__device__ __forceinline__ void ldsm_x4(uint32_t* r, const void* p) {
    uint32_t a = (uint32_t)__cvta_generic_to_shared(p);
    asm volatile("ldmatrix.sync.aligned.m8n8.x4.shared.b16 {%0,%1,%2,%3}, [%4];"
                 : "=r"(r[0]), "=r"(r[1]), "=r"(r[2]), "=r"(r[3]) : "r"(a));
}
__device__ __forceinline__ void ldsm_x4_t(uint32_t* r, const void* p) {
    uint32_t a = (uint32_t)__cvta_generic_to_shared(p);
    asm volatile("ldmatrix.sync.aligned.m8n8.x4.trans.shared.b16 {%0,%1,%2,%3}, [%4];"
                 : "=r"(r[0]), "=r"(r[1]), "=r"(r[2]), "=r"(r[3]) : "r"(a));
}
__device__ __forceinline__ void mma16816(float* c, const uint32_t* a,
                                         uint32_t b0, uint32_t b1) {
    asm volatile("mma.sync.aligned.m16n8k16.row.col.f32.f16.f16.f32 "
                 "{%0,%1,%2,%3}, {%4,%5,%6,%7}, {%8,%9}, {%0,%1,%2,%3};"
                 : "+f"(c[0]), "+f"(c[1]), "+f"(c[2]), "+f"(c[3])
                 : "r"(a[0]), "r"(a[1]), "r"(a[2]), "r"(a[3]), "r"(b0), "r"(b1));
}
__device__ __forceinline__ uint32_t packh2(float a, float b) {
    __half2 h = __floats2half2_rn(a, b);
    return *reinterpret_cast<uint32_t*>(&h);
}
__device__ __forceinline__ void split2h(float a, float b, uint32_t& hi, uint32_t& lo) {
    __half2 h = __floats2half2_rn(a, b);
    float2 hf = __half22float2(h);
    __half2 l = __floats2half2_rn(a - hf.x, b - hf.y);
    hi = *reinterpret_cast<uint32_t*>(&h);
    lo = *reinterpret_cast<uint32_t*>(&l);
}
__device__ __forceinline__ void cp16(void* dst, const void* src) {
    uint32_t d = (uint32_t)__cvta_generic_to_shared(dst);
    asm volatile("cp.async.cg.shared.global [%0], [%1], 16;" :: "r"(d), "l"(src));
}

// ---------------------------------------------------------------------------
// K0a: split x -> fp16 hi/lo
// ---------------------------------------------------------------------------
__global__ __launch_bounds__(256)
void split_x(const float* __restrict__ x)
{
    int i = (blockIdx.x * 256 + threadIdx.x) * 4;
    float4 v = *(const float4*)(x + i);
    uint32_t h0, l0, h1, l1;
    split2h(v.x, v.y, h0, l0);
    split2h(v.z, v.w, h1, l1);
    *(uint32_t*)&g_xh[i]     = h0;  *(uint32_t*)&g_xh[i + 2] = h1;
    *(uint32_t*)&g_xl[i]     = l0;  *(uint32_t*)&g_xl[i + 2] = l1;
}

// K0b: split W (Q weight pre-scaled by 1/sqrt(E))
__global__ __launch_bounds__(256)
void split_w(const float* __restrict__ Wk,
             const float* __restrict__ Wq,
             const float* __restrict__ Wv)
{
    int y = blockIdx.y;
    const float* W = (y == 0) ? Wq : (y == 1) ? Wk : Wv;
    float sc = (y == 0) ? rsqrtf((float)EMB) : 1.0f;
    int i = (blockIdx.x * 256 + threadIdx.x) * 4;
    float4 v = *(const float4*)(W + i);
    uint32_t h0, l0, h1, l1;
    split2h(v.x * sc, v.y * sc, h0, l0);
    split2h(v.z * sc, v.w * sc, h1, l1);
    *(uint32_t*)&g_wh[y][i]     = h0;  *(uint32_t*)&g_wh[y][i + 2] = h1;
    *(uint32_t*)&g_wl[y][i]     = l0;  *(uint32_t*)&g_wl[y][i + 2] = l1;
}

// ---------------------------------------------------------------------------
// K1: QKV GEMM (fp16 x3). CTA 128x64, 8 warps (4 rg x 2 cg), warp tile 32x32,
// k-chunk 64, 2-stage cp.async. Writes q/k/v hi fp16 only.
// stage: Xh[128][72] Xl[128][72] Wh[64][72] Wl[64][72]
// ---------------------------------------------------------------------------
#define BM   128
#define BKC  64
#define XSTR 72
#define WSTR 72
#define SXH  (BM*XSTR)            // 9216
#define SWH  (BKC*WSTR)           // 4608
#define STG_ELEMS (2*SXH + 2*SWH) // 27648 halves = 55296 B

extern __shared__ __half g_sm[];

__device__ __forceinline__ void gemm_load_stage(__half* st, int widx,
                                                int m0, int kc0, int t)
{
    __half* Xh = st;
    __half* Xl = st + SXH;
    __half* Wh = st + 2 * SXH;
    __half* Wl = Wh + SWH;

    int row = t >> 1, off = (t & 1) * 32;
    const __half* sxh = g_xh + (size_t)(m0 + row) * EMB + kc0 + off;
    const __half* sxl = g_xl + (size_t)(m0 + row) * EMB + kc0 + off;
    #pragma unroll
    for (int i = 0; i < 4; i++) {
        cp16(&Xh[row * XSTR + off + i * 8], sxh + i * 8);
        cp16(&Xl[row * XSTR + off + i * 8], sxl + i * 8);
    }

    int wr = t >> 2, wo = (t & 3) * 16;
    const __half* swh = g_wh[widx] + (size_t)(kc0 + wr) * HDIM + wo;
    const __half* swl = g_wl[widx] + (size_t)(kc0 + wr) * HDIM + wo;
    cp16(&Wh[wr * WSTR + wo],     swh);
    cp16(&Wh[wr * WSTR + wo + 8], swh + 8);
    cp16(&Wl[wr * WSTR + wo],     swl);
    cp16(&Wl[wr * WSTR + wo + 8], swl + 8);
}

__global__ __launch_bounds__(256)
void qkv_gemm_mma()
{
    const int widx = blockIdx.y;
    const int m0   = blockIdx.x * BM;
    const int t    = threadIdx.x;
    const int w    = t >> 5;
    const int lane = t & 31;
    const int rg   = w >> 1;
    const int cg   = w & 1;

    const int lrow = (lane & 7) + ((lane >> 3) & 1) * 8;
    const int lcol = (lane >> 4) * 8;

    float c[2][4][4];
    #pragma unroll
    for (int mt = 0; mt < 2; mt++)
        #pragma unroll
        for (int j = 0; j < 4; j++)
            #pragma unroll
            for (int e = 0; e < 4; e++) c[mt][j][e] = 0.f;

    const int NC = EMB / BKC;   // 12

    gemm_load_stage(g_sm, widx, m0, 0, t);
    asm volatile("cp.async.commit_group;");

    for (int kc = 0; kc < NC; kc++) {
        if (kc + 1 < NC) {
            gemm_load_stage(g_sm + ((kc + 1) & 1) * STG_ELEMS, widx, m0, (kc + 1) * BKC, t);
            asm volatile("cp.async.commit_group;");
            asm volatile("cp.async.wait_group 1;");
        } else {
            asm volatile("cp.async.wait_group 0;");
        }
        __syncthreads();

        __half* st = g_sm + (kc & 1) * STG_ELEMS;
        __half* Xh = st;
        __half* Xl = st + SXH;
        __half* Wh = st + 2 * SXH;
        __half* Wl = Wh + SWH;

        #pragma unroll
        for (int kt = 0; kt < 4; kt++) {
            uint32_t ah[2][4], al[2][4];
            #pragma unroll
            for (int mt = 0; mt < 2; mt++) {
                ldsm_x4(ah[mt], &Xh[(rg * 32 + mt * 16 + lrow) * XSTR + kt * 16 + lcol]);
                ldsm_x4(al[mt], &Xl[(rg * 32 + mt * 16 + lrow) * XSTR + kt * 16 + lcol]);
            }
            #pragma unroll
            for (int nt = 0; nt < 2; nt++) {
                uint32_t bh[4], bl[4];
                ldsm_x4_t(bh, &Wh[(kt * 16 + lrow) * WSTR + cg * 32 + nt * 16 + lcol]);
                ldsm_x4_t(bl, &Wl[(kt * 16 + lrow) * WSTR + cg * 32 + nt * 16 + lcol]);
                #pragma unroll
                for (int mt = 0; mt < 2; mt++) {
                    mma16816(c[mt][nt * 2],     ah[mt], bh[0], bh[1]);
                    mma16816(c[mt][nt * 2],     ah[mt], bl[0], bl[1]);
                    mma16816(c[mt][nt * 2],     al[mt], bh[0], bh[1]);
                    mma16816(c[mt][nt * 2 + 1], ah[mt], bh[2], bh[3]);
                    mma16816(c[mt][nt * 2 + 1], ah[mt], bl[2], bl[3]);
                    mma16816(c[mt][nt * 2 + 1], al[mt], bh[2], bh[3]);
                }
            }
        }
        __syncthreads();
    }

    __half* oh = (widx == 0) ? g_qh : (widx == 1) ? g_kh : g_vh;

    #pragma unroll
    for (int mt = 0; mt < 2; mt++) {
        int r0 = m0 + rg * 32 + mt * 16 + (lane >> 2);
        #pragma unroll
        for (int j = 0; j < 4; j++) {
            int col = cg * 32 + j * 8 + 2 * (lane & 3);
            *(uint32_t*)&oh[(size_t)r0 * HDIM + col]       = packh2(c[mt][j][0], c[mt][j][1]);
            *(uint32_t*)&oh[(size_t)(r0 + 8) * HDIM + col] = packh2(c[mt][j][2], c[mt][j][3]);
        }
    }
}

// ---------------------------------------------------------------------------
// K2: plain-fp16 flash attention. BQ=128 (8 warps), BK=64, split-K(2),
// cp.async double-buffered K/V. Unnormalized partials (O, m, l).
// ---------------------------------------------------------------------------
#define BQ   128
#define BK   64
#define STR  72
#define NEG_BIG (-1e30f)
#define MFLOOR  (-1e28f)

__device__ __forceinline__ void attn_load_kv(__half* Kh, __half* Vh,
                                             int b, int k0, int t)
{
    int row = t >> 2, off = (t & 3) * 16;
    const __half* sk = g_kh + (size_t)(b * SEQ + k0 + row) * HDIM + off;
    const __half* sv = g_vh + (size_t)(b * SEQ + k0 + row) * HDIM + off;
    cp16(&Kh[row * STR + off],     sk);
    cp16(&Kh[row * STR + off + 8], sk + 8);
    cp16(&Vh[row * STR + off],     sv);
    cp16(&Vh[row * STR + off + 8], sv + 8);
}

__global__ __launch_bounds__(256)
void attn_kernel()
{
    __shared__ __half sm[2][2][BK * STR];   // [stage][K/V]

    const int b     = blockIdx.y;
    const int tile  = blockIdx.x >> 1;    // 0..15
    const int chunk = blockIdx.x & 1;
    const int q0    = tile * BQ;
    const int t     = threadIdx.x;
    const int w     = t >> 5;
    const int lane  = t & 31;

    // ---- stage Q (hi fp16) into sm[0], read A-frags ----
    __half* sQ = &sm[0][0][0];   // 9216 halves
    {
        int row = t >> 1, off = (t & 1) * 32;
        const uint4* src = (const uint4*)(g_qh + (size_t)(b * SEQ + q0 + row) * HDIM + off);
        uint4* dst = (uint4*)&sQ[row * STR + off];
        #pragma unroll
        for (int i = 0; i < 4; i++) dst[i] = src[i];
    }
    __syncthreads();

    const int lrow = (lane & 7) + ((lane >> 3) & 1) * 8;
    const int lcol = (lane >> 4) * 8;
    uint32_t qf[4][4];
    #pragma unroll
    for (int kc = 0; kc < 4; kc++)
        ldsm_x4(qf[kc], &sQ[(w * 16 + lrow) * STR + kc * 16 + lcol]);
    __syncthreads();   // all warps done reading Q before prefetch overwrites

    float m0 = NEG_BIG, m1 = NEG_BIG, l0 = 0.f, l1 = 0.f;
    float o[8][4];
    #pragma unroll
    for (int j = 0; j < 8; j++)
        #pragma unroll
        for (int e = 0; e < 4; e++) o[j][e] = 0.f;

    const int nkb = 2 * tile + 2;   // 64-key blocks covering keys < q0+128

    int stg = 0;
    attn_load_kv(sm[0][0], sm[0][1], b, chunk * BK, t);
    asm volatile("cp.async.commit_group;");

    for (int kb = chunk; kb < nkb; kb += NCHUNK) {
        const int k0 = kb * BK;
        const int nxt = kb + NCHUNK;
        if (nxt < nkb) {
            attn_load_kv(sm[stg ^ 1][0], sm[stg ^ 1][1], b, nxt * BK, t);
            asm volatile("cp.async.commit_group;");
            asm volatile("cp.async.wait_group 1;");
        } else {
            asm volatile("cp.async.wait_group 0;");
        }
        __syncthreads();

        __half* Kh = sm[stg][0];
        __half* Vh = sm[stg][1];

        // ---- S = Q K^T (fp16, fp32 acc) ----
        float c[8][4];
        #pragma unroll
        for (int j = 0; j < 8; j++)
            #pragma unroll
            for (int e = 0; e < 4; e++) c[j][e] = 0.f;

        #pragma unroll
        for (int kc = 0; kc < 4; kc++) {
            #pragma unroll
            for (int jp = 0; jp < 4; jp++) {
                int krow = 16 * jp + (lane & 7) + (lane >> 4) * 8;
                int kcol = kc * 16 + ((lane >> 3) & 1) * 8;
                uint32_t bh[4];
                ldsm_x4(bh, &Kh[krow * STR + kcol]);
                mma16816(c[2 * jp],     qf[kc], bh[0], bh[1]);
                mma16816(c[2 * jp + 1], qf[kc], bh[2], bh[3]);
            }
        }

        // ---- causal mask (any block that can cross this warp's rows) ----
        if (k0 + BK - 1 > q0 + w * 16) {
            int r0g = q0 + w * 16 + (lane >> 2);
            #pragma unroll
            for (int j = 0; j < 8; j++) {
                int cgl = k0 + 8 * j + 2 * (lane & 3);
                if (cgl     > r0g)     c[j][0] = NEG_BIG;
                if (cgl + 1 > r0g)     c[j][1] = NEG_BIG;
                if (cgl     > r0g + 8) c[j][2] = NEG_BIG;
                if (cgl + 1 > r0g + 8) c[j][3] = NEG_BIG;
            }
        }

        // ---- online softmax (with fully-masked-block floor) ----
        float mx0 = NEG_BIG, mx1 = NEG_BIG;
        #pragma unroll
        for (int j = 0; j < 8; j++) {
            mx0 = fmaxf(mx0, fmaxf(c[j][0], c[j][1]));
            mx1 = fmaxf(mx1, fmaxf(c[j][2], c[j][3]));
        }
        #pragma unroll
        for (int ox = 1; ox <= 2; ox <<= 1) {
            mx0 = fmaxf(mx0, __shfl_xor_sync(0xffffffffu, mx0, ox));
            mx1 = fmaxf(mx1, __shfl_xor_sync(0xffffffffu, mx1, ox));
        }
        float mn0 = fmaxf(fmaxf(m0, mx0), MFLOOR);
        float mn1 = fmaxf(fmaxf(m1, mx1), MFLOOR);
        float corr0 = __expf(m0 - mn0), corr1 = __expf(m1 - mn1);
        m0 = mn0; m1 = mn1;

        float rs0 = 0.f, rs1 = 0.f;
        uint32_t ap[4][4];
        #pragma unroll
        for (int j = 0; j < 8; j++) {
            float p00 = __expf(c[j][0] - mn0);
            float p01 = __expf(c[j][1] - mn0);
            float p10 = __expf(c[j][2] - mn1);
            float p11 = __expf(c[j][3] - mn1);
            rs0 += p00 + p01;
            rs1 += p10 + p11;
            int kc2 = j >> 1, sel = (j & 1) * 2;
            ap[kc2][sel + 0] = packh2(p00, p01);
            ap[kc2][sel + 1] = packh2(p10, p11);
        }
        #pragma unroll
        for (int ox = 1; ox <= 2; ox <<= 1) {
            rs0 += __shfl_xor_sync(0xffffffffu, rs0, ox);
            rs1 += __shfl_xor_sync(0xffffffffu, rs1, ox);
        }
        l0 = l0 * corr0 + rs0;
        l1 = l1 * corr1 + rs1;
        #pragma unroll
        for (int j = 0; j < 8; j++) {
            o[j][0] *= corr0; o[j][1] *= corr0;
            o[j][2] *= corr1; o[j][3] *= corr1;
        }

        // ---- O += P V (fp16) ----
        #pragma unroll
        for (int kc2 = 0; kc2 < 4; kc2++) {
            #pragma unroll
            for (int up = 0; up < 4; up++) {
                int vrow = 16 * kc2 + (lane & 7) + ((lane >> 3) & 1) * 8;
                int vcol = 16 * up + (lane >> 4) * 8;
                uint32_t bv[4];
                ldsm_x4_t(bv, &Vh[vrow * STR + vcol]);
                mma16816(o[2 * up],     ap[kc2], bv[0], bv[1]);
                mma16816(o[2 * up + 1], ap[kc2], bv[2], bv[3]);
            }
        }

        __syncthreads();
        stg ^= 1;
    }

    // ---- write partials ----
    int rl0 = b * SEQ + q0 + w * 16 + (lane >> 2);
    if ((lane & 3) == 0) {
        g_pm[chunk][rl0]     = m0;  g_pl[chunk][rl0]     = l0;
        g_pm[chunk][rl0 + 8] = m1;  g_pl[chunk][rl0 + 8] = l1;
    }
    #pragma unroll
    for (int j = 0; j < 8; j++) {
        int col = 8 * j + 2 * (lane & 3);
        *(float2*)&g_po[chunk][(size_t)rl0 * HDIM + col]       = make_float2(o[j][0], o[j][1]);
        *(float2*)&g_po[chunk][(size_t)(rl0 + 8) * HDIM + col] = make_float2(o[j][2], o[j][3]);
    }
}

// ---------------------------------------------------------------------------
// K3: combine split-K partials.
// ---------------------------------------------------------------------------
__global__ __launch_bounds__(256)
void combine_kernel(float* __restrict__ out)
{
    int idx = blockIdx.x * 256 + threadIdx.x;   // over ROWS*32
    int row = idx >> 5;
    int col = (idx & 31) * 2;

    float mx = NEG_BIG;
    #pragma unroll
    for (int i = 0; i < NCHUNK; i++) mx = fmaxf(mx, g_pm[i][row]);

    float l = 0.f, ox = 0.f, oy = 0.f;
    #pragma unroll
    for (int i = 0; i < NCHUNK; i++) {
        float s = __expf(g_pm[i][row] - mx);
        l += s * g_pl[i][row];
        float2 p = *(const float2*)&g_po[i][(size_t)row * HDIM + col];
        ox += s * p.x;
        oy += s * p.y;
    }
    float inv = 1.0f / l;
    *(float2*)&out[(size_t)row * HDIM + col] = make_float2(ox * inv, oy * inv);
}

// ---------------------------------------------------------------------------
extern "C" void kernel_launch(void* const* d_in, const int* in_sizes, int n_in,
                              void* d_out, int out_size)
{
    const float* x  = (const float*)d_in[0];
    const float* Wk = (const float*)d_in[1];
    const float* Wq = (const float*)d_in[2];
    const float* Wv = (const float*)d_in[3];
    float* out = (float*)d_out;

    split_x<<<(ROWS * EMB / 4) / 256, 256>>>(x);
    dim3 wgrid((EMB * HDIM / 4) / 256, 3);
    split_w<<<wgrid, 256>>>(Wk, Wq, Wv);

    const int gsmem = 2 * STG_ELEMS * (int)sizeof(__half);   // 110592 B
    cudaFuncSetAttribute(qkv_gemm_mma, cudaFuncAttributeMaxDynamicSharedMemorySize, gsmem);
    dim3 ggrid(ROWS / BM, 3);
    qkv_gemm_mma<<<ggrid, 256, gsmem>>>();

    dim3 agrid((SEQ / BQ) * NCHUNK, BATCH);
    attn_kernel<<<agrid, 256>>>();

    combine_kernel<<<(ROWS * 32) / 256, 256>>>(out);
}

// round 9
// speedup vs baseline: 2.5872x; 1.4516x over previous
#include <cuda_runtime.h>
#include <cuda_fp16.h>
#include <cstdint>

// B=4, T=2048, E=768, H=64 — causal single-head attention, fp32 out.
// split_w (fp16 hi, q-scaled, N=192 fused) | QKV GEMM (fp32 x staged raw,
// A-frags built in regs as fp16 hi/lo, 2-term, 1 wave) | fp16 flash attention
// (BQ=128, split-K 4, cp.async) | combine.

#define BATCH 4
#define SEQ   2048
#define EMB   768
#define HDIM  64
#define ROWS  (BATCH*SEQ)   // 8192
#define NCHUNK 4

__device__ __half g_wh[EMB*192];                                  // [k][q|k|v]
__device__ __half g_qh[ROWS*HDIM], g_kh[ROWS*HDIM], g_vh[ROWS*HDIM];
__device__ float g_pm[NCHUNK][ROWS], g_pl[NCHUNK][ROWS], g_po[NCHUNK][ROWS*HDIM];

// ---------------- helpers (sm_80+ baseline PTX) ------------------------------
__device__ __forceinline__ void ldsm_x4(uint32_t* r, const void* p) {
    uint32_t a = (uint32_t)__cvta_generic_to_shared(p);
    asm volatile("ldmatrix.sync.aligned.m8n8.x4.shared.b16 {%0,%1,%2,%3}, [%4];"
                 : "=r"(r[0]), "=r"(r[1]), "=r"(r[2]), "=r"(r[3]) : "r"(a));
}
__device__ __forceinline__ void ldsm_x4_t(uint32_t* r, const void* p) {
    uint32_t a = (uint32_t)__cvta_generic_to_shared(p);
    asm volatile("ldmatrix.sync.aligned.m8n8.x4.trans.shared.b16 {%0,%1,%2,%3}, [%4];"
                 : "=r"(r[0]), "=r"(r[1]), "=r"(r[2]), "=r"(r[3]) : "r"(a));
}
__device__ __forceinline__ void mma16816(float* c, const uint32_t* a,
                                         uint32_t b0, uint32_t b1) {
    asm volatile("mma.sync.aligned.m16n8k16.row.col.f32.f16.f16.f32 "
                 "{%0,%1,%2,%3}, {%4,%5,%6,%7}, {%8,%9}, {%0,%1,%2,%3};"
                 : "+f"(c[0]), "+f"(c[1]), "+f"(c[2]), "+f"(c[3])
                 : "r"(a[0]), "r"(a[1]), "r"(a[2]), "r"(a[3]), "r"(b0), "r"(b1));
}
__device__ __forceinline__ uint32_t packh2(float a, float b) {
    __half2 h = __floats2half2_rn(a, b);
    return *reinterpret_cast<uint32_t*>(&h);
}
__device__ __forceinline__ void split2h(float a, float b, uint32_t& hi, uint32_t& lo) {
    __half2 h = __floats2half2_rn(a, b);
    float2 hf = __half22float2(h);
    __half2 l = __floats2half2_rn(a - hf.x, b - hf.y);
    hi = *reinterpret_cast<uint32_t*>(&h);
    lo = *reinterpret_cast<uint32_t*>(&l);
}
__device__ __forceinline__ void cp16(void* dst, const void* src) {
    uint32_t d = (uint32_t)__cvta_generic_to_shared(dst);
    asm volatile("cp.async.cg.shared.global [%0], [%1], 16;" :: "r"(d), "l"(src));
}

extern __shared__ char smbase[];

// ---------------------------------------------------------------------------
// K0: split W -> fp16 hi, fused [k][192] layout, Q pre-scaled by 1/sqrt(E).
// ---------------------------------------------------------------------------
__global__ __launch_bounds__(256)
void split_w(const float* __restrict__ Wk,
             const float* __restrict__ Wq,
             const float* __restrict__ Wv)
{
    int idx = blockIdx.x * 256 + threadIdx.x;       // over 3*EMB*HDIM/2
    int widx = idx / (EMB * HDIM / 2);
    int e    = (idx % (EMB * HDIM / 2)) * 2;
    const float* W = (widx == 0) ? Wq : (widx == 1) ? Wk : Wv;
    float sc = (widx == 0) ? rsqrtf((float)EMB) : 1.0f;
    int k = e / HDIM, n = e % HDIM;
    float2 v = *(const float2*)(W + e);
    *(uint32_t*)&g_wh[k * 192 + widx * 64 + n] = packh2(v.x * sc, v.y * sc);
}

// ---------------------------------------------------------------------------
// K1: fused QKV GEMM. CTA = 64 rows x 192 cols, 256 thr = 8 warps (2rg x 4cg),
// warp tile 32x48. x staged as RAW fp32 (cp.async, double buffer); A-frags
// built manually in registers as fp16 hi/lo. C = (xh + xl) * Wh.
// stage: Xf[64][72] fp32 (18432B) + Wh[64][200] fp16 (25600B) = 44032B; x2.
// ---------------------------------------------------------------------------
#define BM    64
#define BKC   64
#define XSTRF 72
#define WSTR  200
#define STGB  44032

__device__ __forceinline__ void gemm_load_stage(char* st, const float* x,
                                                int m0, int kc0, int t)
{
    float*  Xf = (float*)st;
    __half* Wh = (__half*)(st + BM * XSTRF * 4);

    int row = t >> 2, coff = (t & 3) * 16;
    const float* sx = x + (size_t)(m0 + row) * EMB + kc0 + coff;
    #pragma unroll
    for (int i = 0; i < 4; i++)
        cp16(&Xf[row * XSTRF + coff + i * 4], sx + i * 4);

    int wr = t >> 2, woff = (t & 3) * 48;
    const __half* sw = g_wh + (size_t)(kc0 + wr) * 192 + woff;
    #pragma unroll
    for (int i = 0; i < 6; i++)
        cp16(&Wh[wr * WSTR + woff + i * 8], sw + i * 8);
}

__global__ __launch_bounds__(256)
void qkv_gemm_mma(const float* __restrict__ x)
{
    const int m0   = blockIdx.x * BM;
    const int t    = threadIdx.x;
    const int w    = t >> 5;
    const int lane = t & 31;
    const int rg   = w >> 2;        // 0..1 (32 rows)
    const int cg   = w & 3;         // 0..3 (48 cols)

    const int fr = lane >> 2;             // frag row 0..7
    const int fc = (lane & 3) * 2;        // frag col 0,2,4,6
    const int lrow = (lane & 7) + ((lane >> 3) & 1) * 8;
    const int lcol = (lane >> 4) * 8;

    float c[2][6][4];
    #pragma unroll
    for (int mt = 0; mt < 2; mt++)
        #pragma unroll
        for (int j = 0; j < 6; j++)
            #pragma unroll
            for (int e = 0; e < 4; e++) c[mt][j][e] = 0.f;

    const int NC = EMB / BKC;   // 12

    gemm_load_stage(smbase, x, m0, 0, t);
    asm volatile("cp.async.commit_group;");

    for (int kc = 0; kc < NC; kc++) {
        if (kc + 1 < NC) {
            gemm_load_stage(smbase + ((kc + 1) & 1) * STGB, x, m0, (kc + 1) * BKC, t);
            asm volatile("cp.async.commit_group;");
            asm volatile("cp.async.wait_group 1;");
        } else {
            asm volatile("cp.async.wait_group 0;");
        }
        __syncthreads();

        char*   st = smbase + (kc & 1) * STGB;
        float*  Xf = (float*)st;
        __half* Wh = (__half*)(st + BM * XSTRF * 4);

        #pragma unroll
        for (int kt = 0; kt < 4; kt++) {
            uint32_t ah[2][4], al[2][4];
            #pragma unroll
            for (int mt = 0; mt < 2; mt++) {
                const float* base = &Xf[(rg * 32 + mt * 16 + fr) * XSTRF + kt * 16 + fc];
                float2 v00 = *(const float2*)(base);
                float2 v10 = *(const float2*)(base + 8 * XSTRF);
                float2 v01 = *(const float2*)(base + 8);
                float2 v11 = *(const float2*)(base + 8 * XSTRF + 8);
                split2h(v00.x, v00.y, ah[mt][0], al[mt][0]);
                split2h(v10.x, v10.y, ah[mt][1], al[mt][1]);
                split2h(v01.x, v01.y, ah[mt][2], al[mt][2]);
                split2h(v11.x, v11.y, ah[mt][3], al[mt][3]);
            }
            #pragma unroll
            for (int nt = 0; nt < 3; nt++) {
                uint32_t bh[4];
                ldsm_x4_t(bh, &Wh[(kt * 16 + lrow) * WSTR + cg * 48 + nt * 16 + lcol]);
                #pragma unroll
                for (int mt = 0; mt < 2; mt++) {
                    mma16816(c[mt][nt * 2],     ah[mt], bh[0], bh[1]);
                    mma16816(c[mt][nt * 2],     al[mt], bh[0], bh[1]);
                    mma16816(c[mt][nt * 2 + 1], ah[mt], bh[2], bh[3]);
                    mma16816(c[mt][nt * 2 + 1], al[mt], bh[2], bh[3]);
                }
            }
        }
        __syncthreads();
    }

    #pragma unroll
    for (int mt = 0; mt < 2; mt++) {
        int r0 = m0 + rg * 32 + mt * 16 + (lane >> 2);
        #pragma unroll
        for (int j = 0; j < 6; j++) {
            int col_local = cg * 48 + j * 8 + 2 * (lane & 3);
            int widx = col_local >> 6;
            int col  = col_local & 63;
            __half* oh = (widx == 0) ? g_qh : (widx == 1) ? g_kh : g_vh;
            *(uint32_t*)&oh[(size_t)r0 * HDIM + col]       = packh2(c[mt][j][0], c[mt][j][1]);
            *(uint32_t*)&oh[(size_t)(r0 + 8) * HDIM + col] = packh2(c[mt][j][2], c[mt][j][3]);
        }
    }
}

// ---------------------------------------------------------------------------
// K2: fp16 flash attention. BQ=128 (8 warps), BK=64, split-K(4),
// cp.async double-buffered K/V, Q in separate smem region.
// smem: sQ[128*72] + stages[2][K,V][64*72] halves = 55296 B dynamic.
// ---------------------------------------------------------------------------
#define BQ   128
#define BK   64
#define STR  72
#define NEG_BIG (-1e30f)
#define MFLOOR  (-1e28f)

__device__ __forceinline__ void attn_load_kv(__half* Kh, __half* Vh,
                                             int b, int k0, int t)
{
    int row = t >> 2, off = (t & 3) * 16;
    const __half* sk = g_kh + (size_t)(b * SEQ + k0 + row) * HDIM + off;
    const __half* sv = g_vh + (size_t)(b * SEQ + k0 + row) * HDIM + off;
    cp16(&Kh[row * STR + off],     sk);
    cp16(&Kh[row * STR + off + 8], sk + 8);
    cp16(&Vh[row * STR + off],     sv);
    cp16(&Vh[row * STR + off + 8], sv + 8);
}

__global__ __launch_bounds__(256)
void attn_kernel()
{
    __half* sQ = (__half*)smbase;                     // 9216 halves
    __half* sKV[2][2];
    #pragma unroll
    for (int s = 0; s < 2; s++)
        #pragma unroll
        for (int kv = 0; kv < 2; kv++)
            sKV[s][kv] = (__half*)smbase + BQ * STR + (s * 2 + kv) * BK * STR;

    const int b     = blockIdx.y;
    const int tile  = blockIdx.x >> 2;    // 0..15
    const int chunk = blockIdx.x & 3;
    const int q0    = tile * BQ;
    const int t     = threadIdx.x;
    const int w     = t >> 5;
    const int lane  = t & 31;

    const int nkb = 2 * tile + 2;          // 64-key blocks for this tile
    const bool has_work = (chunk < nkb);

    // prefetch first K/V while staging Q
    if (has_work && t < 256) attn_load_kv(sKV[0][0], sKV[0][1], b, chunk * BK, t);
    asm volatile("cp.async.commit_group;");

    {
        int row = t >> 1, off = (t & 1) * 32;
        const uint4* src = (const uint4*)(g_qh + (size_t)(b * SEQ + q0 + row) * HDIM + off);
        uint4* dst = (uint4*)&sQ[row * STR + off];
        #pragma unroll
        for (int i = 0; i < 4; i++) dst[i] = src[i];
    }
    __syncthreads();

    const int lrow = (lane & 7) + ((lane >> 3) & 1) * 8;
    const int lcol = (lane >> 4) * 8;
    uint32_t qf[4][4];
    #pragma unroll
    for (int kc = 0; kc < 4; kc++)
        ldsm_x4(qf[kc], &sQ[(w * 16 + lrow) * STR + kc * 16 + lcol]);

    float m0 = NEG_BIG, m1 = NEG_BIG, l0 = 0.f, l1 = 0.f;
    float o[8][4];
    #pragma unroll
    for (int j = 0; j < 8; j++)
        #pragma unroll
        for (int e = 0; e < 4; e++) o[j][e] = 0.f;

    int stg = 0;
    for (int kb = chunk; kb < nkb; kb += NCHUNK) {
        const int k0 = kb * BK;
        const int nxt = kb + NCHUNK;
        if (nxt < nkb) {
            attn_load_kv(sKV[stg ^ 1][0], sKV[stg ^ 1][1], b, nxt * BK, t);
            asm volatile("cp.async.commit_group;");
            asm volatile("cp.async.wait_group 1;");
        } else {
            asm volatile("cp.async.wait_group 0;");
        }
        __syncthreads();

        __half* Kh = sKV[stg][0];
        __half* Vh = sKV[stg][1];

        // ---- S = Q K^T (fp16, fp32 acc) ----
        float c[8][4];
        #pragma unroll
        for (int j = 0; j < 8; j++)
            #pragma unroll
            for (int e = 0; e < 4; e++) c[j][e] = 0.f;

        #pragma unroll
        for (int kc = 0; kc < 4; kc++) {
            #pragma unroll
            for (int jp = 0; jp < 4; jp++) {
                int krow = 16 * jp + (lane & 7) + (lane >> 4) * 8;
                int kcol = kc * 16 + ((lane >> 3) & 1) * 8;
                uint32_t bh[4];
                ldsm_x4(bh, &Kh[krow * STR + kcol]);
                mma16816(c[2 * jp],     qf[kc], bh[0], bh[1]);
                mma16816(c[2 * jp + 1], qf[kc], bh[2], bh[3]);
            }
        }

        // ---- causal mask ----
        if (k0 + BK - 1 > q0 + w * 16) {
            int r0g = q0 + w * 16 + (lane >> 2);
            #pragma unroll
            for (int j = 0; j < 8; j++) {
                int cgl = k0 + 8 * j + 2 * (lane & 3);
                if (cgl     > r0g)     c[j][0] = NEG_BIG;
                if (cgl + 1 > r0g)     c[j][1] = NEG_BIG;
                if (cgl     > r0g + 8) c[j][2] = NEG_BIG;
                if (cgl + 1 > r0g + 8) c[j][3] = NEG_BIG;
            }
        }

        // ---- online softmax (fully-masked-block floor) ----
        float mx0 = NEG_BIG, mx1 = NEG_BIG;
        #pragma unroll
        for (int j = 0; j < 8; j++) {
            mx0 = fmaxf(mx0, fmaxf(c[j][0], c[j][1]));
            mx1 = fmaxf(mx1, fmaxf(c[j][2], c[j][3]));
        }
        #pragma unroll
        for (int ox = 1; ox <= 2; ox <<= 1) {
            mx0 = fmaxf(mx0, __shfl_xor_sync(0xffffffffu, mx0, ox));
            mx1 = fmaxf(mx1, __shfl_xor_sync(0xffffffffu, mx1, ox));
        }
        float mn0 = fmaxf(fmaxf(m0, mx0), MFLOOR);
        float mn1 = fmaxf(fmaxf(m1, mx1), MFLOOR);
        float corr0 = __expf(m0 - mn0), corr1 = __expf(m1 - mn1);
        m0 = mn0; m1 = mn1;

        float rs0 = 0.f, rs1 = 0.f;
        uint32_t ap[4][4];
        #pragma unroll
        for (int j = 0; j < 8; j++) {
            float p00 = __expf(c[j][0] - mn0);
            float p01 = __expf(c[j][1] - mn0);
            float p10 = __expf(c[j][2] - mn1);
            float p11 = __expf(c[j][3] - mn1);
            rs0 += p00 + p01;
            rs1 += p10 + p11;
            int kc2 = j >> 1, sel = (j & 1) * 2;
            ap[kc2][sel + 0] = packh2(p00, p01);
            ap[kc2][sel + 1] = packh2(p10, p11);
        }
        #pragma unroll
        for (int ox = 1; ox <= 2; ox <<= 1) {
            rs0 += __shfl_xor_sync(0xffffffffu, rs0, ox);
            rs1 += __shfl_xor_sync(0xffffffffu, rs1, ox);
        }
        l0 = l0 * corr0 + rs0;
        l1 = l1 * corr1 + rs1;
        #pragma unroll
        for (int j = 0; j < 8; j++) {
            o[j][0] *= corr0; o[j][1] *= corr0;
            o[j][2] *= corr1; o[j][3] *= corr1;
        }

        // ---- O += P V (fp16) ----
        #pragma unroll
        for (int kc2 = 0; kc2 < 4; kc2++) {
            #pragma unroll
            for (int up = 0; up < 4; up++) {
                int vrow = 16 * kc2 + (lane & 7) + ((lane >> 3) & 1) * 8;
                int vcol = 16 * up + (lane >> 4) * 8;
                uint32_t bv[4];
                ldsm_x4_t(bv, &Vh[vrow * STR + vcol]);
                mma16816(o[2 * up],     ap[kc2], bv[0], bv[1]);
                mma16816(o[2 * up + 1], ap[kc2], bv[2], bv[3]);
            }
        }

        __syncthreads();
        stg ^= 1;
    }

    // ---- write partials ----
    int rl0 = b * SEQ + q0 + w * 16 + (lane >> 2);
    if ((lane & 3) == 0) {
        g_pm[chunk][rl0]     = m0;  g_pl[chunk][rl0]     = l0;
        g_pm[chunk][rl0 + 8] = m1;  g_pl[chunk][rl0 + 8] = l1;
    }
    #pragma unroll
    for (int j = 0; j < 8; j++) {
        int col = 8 * j + 2 * (lane & 3);
        *(float2*)&g_po[chunk][(size_t)rl0 * HDIM + col]       = make_float2(o[j][0], o[j][1]);
        *(float2*)&g_po[chunk][(size_t)(rl0 + 8) * HDIM + col] = make_float2(o[j][2], o[j][3]);
    }
}

// ---------------------------------------------------------------------------
// K3: combine split-K partials.
// ---------------------------------------------------------------------------
__global__ __launch_bounds__(256)
void combine_kernel(float* __restrict__ out)
{
    int idx = blockIdx.x * 256 + threadIdx.x;   // over ROWS*32
    int row = idx >> 5;
    int col = (idx & 31) * 2;

    float mx = NEG_BIG;
    #pragma unroll
    for (int i = 0; i < NCHUNK; i++) mx = fmaxf(mx, g_pm[i][row]);

    float l = 0.f, ox = 0.f, oy = 0.f;
    #pragma unroll
    for (int i = 0; i < NCHUNK; i++) {
        float s = __expf(g_pm[i][row] - mx);
        l += s * g_pl[i][row];
        float2 p = *(const float2*)&g_po[i][(size_t)row * HDIM + col];
        ox += s * p.x;
        oy += s * p.y;
    }
    float inv = 1.0f / l;
    *(float2*)&out[(size_t)row * HDIM + col] = make_float2(ox * inv, oy * inv);
}

// ---------------------------------------------------------------------------
extern "C" void kernel_launch(void* const* d_in, const int* in_sizes, int n_in,
                              void* d_out, int out_size)
{
    const float* x  = (const float*)d_in[0];
    const float* Wk = (const float*)d_in[1];
    const float* Wq = (const float*)d_in[2];
    const float* Wv = (const float*)d_in[3];
    float* out = (float*)d_out;

    split_w<<<(3 * EMB * HDIM / 2) / 256, 256>>>(Wk, Wq, Wv);

    const int gsmem = 2 * STGB;   // 88064 B
    cudaFuncSetAttribute(qkv_gemm_mma, cudaFuncAttributeMaxDynamicSharedMemorySize, gsmem);
    qkv_gemm_mma<<<ROWS / BM, 256, gsmem>>>(x);

    const int asmem = (BQ * STR + 4 * BK * STR) * (int)sizeof(__half);  // 55296
    cudaFuncSetAttribute(attn_kernel, cudaFuncAttributeMaxDynamicSharedMemorySize, asmem);
    dim3 agrid((SEQ / BQ) * NCHUNK, BATCH);
    attn_kernel<<<agrid, 256, asmem>>>();

    combine_kernel<<<(ROWS * 32) / 256, 256>>>(out);
}